// round 8
// baseline (speedup 1.0000x reference)
#include <cuda_runtime.h>

#define BB 32
#define CC 512
#define HC 128
#define HW 4096
#define NPLANE (BB * CC)
#define EPS_BN 0.001f

// scratch (no device allocations allowed anywhere)
__device__ float g_s[BB * CC];      // pooled means [B, C]
__device__ float g_es[BB * CC];     // e * scale2   [B, C]
__device__ float g_shift[CC];       // shift2       [C]

// ---------------------------------------------------------------------------
// Kernel 1: per-plane mean, full grid. Default caching -> x streams through
// L2 and the tail (~126MB, highest planes) stays resident for kernel 3.
// ---------------------------------------------------------------------------
__global__ void __launch_bounds__(256) se_reduce(const float* __restrict__ x) {
    const int plane = blockIdx.x;
    const float4* xp = reinterpret_cast<const float4*>(x + (size_t)plane * HW);

    float sum = 0.f;
#pragma unroll
    for (int i = 0; i < HW / 4 / 256; i++) {
        float4 v = xp[i * 256 + threadIdx.x];
        sum += (v.x + v.y) + (v.z + v.w);
    }
#pragma unroll
    for (int o = 16; o > 0; o >>= 1)
        sum += __shfl_down_sync(0xffffffffu, sum, o);

    __shared__ float red[8];
    if ((threadIdx.x & 31) == 0) red[threadIdx.x >> 5] = sum;
    __syncthreads();
    if (threadIdx.x == 0) {
        float s = 0.f;
#pragma unroll
        for (int i = 0; i < 8; i++) s += red[i];
        g_s[plane] = s * (1.0f / HW);
    }
}

// ---------------------------------------------------------------------------
// Kernel 2: excitation MLP, one block per batch (32 blocks). Warp-cooperative
// coalesced dot products.
// ---------------------------------------------------------------------------
__global__ void __launch_bounds__(256) se_excite(
    const float* __restrict__ w1, const float* __restrict__ g1,
    const float* __restrict__ b1, const float* __restrict__ m1,
    const float* __restrict__ v1, const float* __restrict__ w2,
    const float* __restrict__ g2, const float* __restrict__ b2,
    const float* __restrict__ m2, const float* __restrict__ v2) {
    __shared__ float s_s[CC];
    __shared__ float s_h[HC];

    const int b    = blockIdx.x;
    const int wid  = threadIdx.x >> 5;
    const int lane = threadIdx.x & 31;

    for (int i = threadIdx.x; i < CC; i += 256) s_s[i] = g_s[b * CC + i];
    __syncthreads();

#pragma unroll 2
    for (int r = 0; r < 16; r++) {
        const int j = wid * 16 + r;
        const float* wr = w1 + j * CC;
        float acc = 0.f;
#pragma unroll
        for (int i = 0; i < CC / 32; i++)
            acc = fmaf(wr[lane + 32 * i], s_s[lane + 32 * i], acc);
#pragma unroll
        for (int o = 16; o > 0; o >>= 1)
            acc += __shfl_down_sync(0xffffffffu, acc, o);
        if (lane == 0) {
            float hv = (acc - m1[j]) * (g1[j] * rsqrtf(v1[j] + EPS_BN)) + b1[j];
            s_h[j] = fmaxf(hv, 0.f);
        }
    }
    __syncthreads();

#pragma unroll 2
    for (int r = 0; r < 64; r++) {
        const int c = wid * 64 + r;
        const float* wr = w2 + c * HC;
        float acc = 0.f;
#pragma unroll
        for (int i = 0; i < HC / 32; i++)
            acc = fmaf(wr[lane + 32 * i], s_h[lane + 32 * i], acc);
#pragma unroll
        for (int o = 16; o > 0; o >>= 1)
            acc += __shfl_down_sync(0xffffffffu, acc, o);
        if (lane == 0) {
            const float sc2 = g2[c] * rsqrtf(v2[c] + EPS_BN);
            g_es[b * CC + c] = acc * sc2;
            if (b == 0) g_shift[c] = fmaf(-m2[c], sc2, b2[c]);
        }
    }
}

// ---------------------------------------------------------------------------
// Kernel 3: y = x*es + shift, full grid, REVERSED plane order so the first
// waves read the x tail that kernel 1 left in L2. 2 planes per block,
// 8 front-batched ldcg loads (MLP=8). Stores are WRITE-THROUGH (__stwt):
// no L2 allocation for y, so L2 stays dedicated to x reads.
// ---------------------------------------------------------------------------
__global__ void __launch_bounds__(256) se_scale(const float* __restrict__ x,
                                                float* __restrict__ y) {
    // reversed: block 0 handles the last 2 planes (freshest in L2)
    const int plane0 = NPLANE - 2 - blockIdx.x * 2;

    float es[2], sh[2];
#pragma unroll
    for (int p = 0; p < 2; p++) {
        es[p] = g_es[plane0 + p];
        sh[p] = g_shift[(plane0 + p) & (CC - 1)];
    }

    const size_t base = (size_t)plane0 * (HW / 4);
    const float4* xp = reinterpret_cast<const float4*>(x) + base + threadIdx.x;
    float4*       yp = reinterpret_cast<float4*>(y) + base + threadIdx.x;

    float4 v[8];
#pragma unroll
    for (int i = 0; i < 8; i++) v[i] = __ldcg(xp + i * 256);

#pragma unroll
    for (int i = 0; i < 8; i++) {
        const float e = es[i >> 2], s = sh[i >> 2];
        float4 o;
        o.x = fmaf(v[i].x, e, s);
        o.y = fmaf(v[i].y, e, s);
        o.z = fmaf(v[i].z, e, s);
        o.w = fmaf(v[i].w, e, s);
        __stwt(yp + i * 256, o);
    }
}

// ---------------------------------------------------------------------------
extern "C" void kernel_launch(void* const* d_in, const int* in_sizes, int n_in,
                              void* d_out, int out_size) {
    const float* x  = (const float*)d_in[0];
    const float* w1 = (const float*)d_in[1];
    const float* g1 = (const float*)d_in[2];
    const float* b1 = (const float*)d_in[3];
    const float* m1 = (const float*)d_in[4];
    const float* v1 = (const float*)d_in[5];
    const float* w2 = (const float*)d_in[6];
    const float* g2 = (const float*)d_in[7];
    const float* b2 = (const float*)d_in[8];
    const float* m2 = (const float*)d_in[9];
    const float* v2 = (const float*)d_in[10];
    float* y = (float*)d_out;

    se_reduce<<<NPLANE, 256>>>(x);
    se_excite<<<BB, 256>>>(w1, g1, b1, m1, v1, w2, g2, b2, m2, v2);
    se_scale<<<NPLANE / 2, 256>>>(x, y);
}

// round 10
// speedup vs baseline: 1.0036x; 1.0036x over previous
#include <cuda_runtime.h>

#define BB 32
#define CC 512
#define HC 128
#define HW 4096
#define NPLANE (BB * CC)
#define KEEP 7168                    /* planes protected in L2: 7168*16KB = 112MB */
#define CUTOFF (NPLANE - KEEP)       /* planes >= CUTOFF stay L2-resident        */
#define EPS_BN 0.001f

// scratch (no device allocations allowed anywhere)
__device__ float g_s[BB * CC];      // pooled means [B, C]
__device__ float g_es[BB * CC];     // e * scale2   [B, C]
__device__ float g_shift[CC];       // shift2       [C]

// ---------------------------------------------------------------------------
// Kernel 1: per-plane mean. Planes < CUTOFF stream (__ldcs, evict-first) so
// they don't evict the protected tail; planes >= CUTOFF use __ldcg and are
// left resident in L2 for kernel 3.
// ---------------------------------------------------------------------------
__global__ void __launch_bounds__(256) se_reduce(const float* __restrict__ x) {
    const int plane = blockIdx.x;
    const bool keep = (plane >= CUTOFF);
    const float4* xp = reinterpret_cast<const float4*>(x + (size_t)plane * HW)
                       + threadIdx.x;

    float sum = 0.f;
    if (keep) {
#pragma unroll
        for (int i = 0; i < 4; i++) {
            float4 v = __ldcg(xp + i * 256);
            sum += (v.x + v.y) + (v.z + v.w);
        }
    } else {
#pragma unroll
        for (int i = 0; i < 4; i++) {
            float4 v = __ldcs(xp + i * 256);
            sum += (v.x + v.y) + (v.z + v.w);
        }
    }
#pragma unroll
    for (int o = 16; o > 0; o >>= 1)
        sum += __shfl_down_sync(0xffffffffu, sum, o);

    __shared__ float red[8];
    if ((threadIdx.x & 31) == 0) red[threadIdx.x >> 5] = sum;
    __syncthreads();
    if (threadIdx.x == 0) {
        float s = 0.f;
#pragma unroll
        for (int i = 0; i < 8; i++) s += red[i];
        g_s[plane] = s * (1.0f / HW);
    }
}

// ---------------------------------------------------------------------------
// Kernel 2: excitation MLP, one block per batch. Warp-cooperative coalesced
// dot products.
// ---------------------------------------------------------------------------
__global__ void __launch_bounds__(256) se_excite(
    const float* __restrict__ w1, const float* __restrict__ g1,
    const float* __restrict__ b1, const float* __restrict__ m1,
    const float* __restrict__ v1, const float* __restrict__ w2,
    const float* __restrict__ g2, const float* __restrict__ b2,
    const float* __restrict__ m2, const float* __restrict__ v2) {
    __shared__ float s_s[CC];
    __shared__ float s_h[HC];

    const int b    = blockIdx.x;
    const int wid  = threadIdx.x >> 5;
    const int lane = threadIdx.x & 31;

    for (int i = threadIdx.x; i < CC; i += 256) s_s[i] = g_s[b * CC + i];
    __syncthreads();

#pragma unroll 2
    for (int r = 0; r < 16; r++) {
        const int j = wid * 16 + r;
        const float* wr = w1 + j * CC;
        float acc = 0.f;
#pragma unroll
        for (int i = 0; i < CC / 32; i++)
            acc = fmaf(wr[lane + 32 * i], s_s[lane + 32 * i], acc);
#pragma unroll
        for (int o = 16; o > 0; o >>= 1)
            acc += __shfl_down_sync(0xffffffffu, acc, o);
        if (lane == 0) {
            float hv = (acc - m1[j]) * (g1[j] * rsqrtf(v1[j] + EPS_BN)) + b1[j];
            s_h[j] = fmaxf(hv, 0.f);
        }
    }
    __syncthreads();

#pragma unroll 2
    for (int r = 0; r < 64; r++) {
        const int c = wid * 64 + r;
        const float* wr = w2 + c * HC;
        float acc = 0.f;
#pragma unroll
        for (int i = 0; i < HC / 32; i++)
            acc = fmaf(wr[lane + 32 * i], s_h[lane + 32 * i], acc);
#pragma unroll
        for (int o = 16; o > 0; o >>= 1)
            acc += __shfl_down_sync(0xffffffffu, acc, o);
        if (lane == 0) {
            const float sc2 = g2[c] * rsqrtf(v2[c] + EPS_BN);
            g_es[b * CC + c] = acc * sc2;
            if (b == 0) g_shift[c] = fmaf(-m2[c], sc2, b2[c]);
        }
    }
}

// ---------------------------------------------------------------------------
// Kernel 3: y = x*es + shift. FOUR planes per block (4*1024 float4 = 16
// loads/thread), REVERSED order so the first waves consume the protected L2
// tail. 16 front-batched loads then 16 back-to-back stores: long
// uninterrupted read/write bursts. Sub-cutoff planes read evict-first.
// ---------------------------------------------------------------------------
__global__ void __launch_bounds__(256) se_scale(const float* __restrict__ x,
                                                float* __restrict__ y) {
    const int plane0 = NPLANE - 4 - blockIdx.x * 4;   // reversed, 4 planes/block

    float es[4], sh[4];
#pragma unroll
    for (int p = 0; p < 4; p++) {
        es[p] = g_es[plane0 + p];
        sh[p] = g_shift[(plane0 + p) & (CC - 1)];
    }

    const size_t base = (size_t)plane0 * (HW / 4);
    const float4* xp = reinterpret_cast<const float4*>(x) + base + threadIdx.x;
    float4*       yp = reinterpret_cast<float4*>(y) + base + threadIdx.x;

    float4 v[16];
    if (plane0 >= CUTOFF) {
#pragma unroll
        for (int i = 0; i < 16; i++) v[i] = __ldcg(xp + i * 256);
    } else {
#pragma unroll
        for (int i = 0; i < 16; i++) v[i] = __ldcs(xp + i * 256);
    }

#pragma unroll
    for (int i = 0; i < 16; i++) {
        const float e = es[i >> 2], s = sh[i >> 2];   // (i*256+t)/1024 == i>>2
        float4 o;
        o.x = fmaf(v[i].x, e, s);
        o.y = fmaf(v[i].y, e, s);
        o.z = fmaf(v[i].z, e, s);
        o.w = fmaf(v[i].w, e, s);
        __stcs(yp + i * 256, o);
    }
}

// ---------------------------------------------------------------------------
extern "C" void kernel_launch(void* const* d_in, const int* in_sizes, int n_in,
                              void* d_out, int out_size) {
    const float* x  = (const float*)d_in[0];
    const float* w1 = (const float*)d_in[1];
    const float* g1 = (const float*)d_in[2];
    const float* b1 = (const float*)d_in[3];
    const float* m1 = (const float*)d_in[4];
    const float* v1 = (const float*)d_in[5];
    const float* w2 = (const float*)d_in[6];
    const float* g2 = (const float*)d_in[7];
    const float* b2 = (const float*)d_in[8];
    const float* m2 = (const float*)d_in[9];
    const float* v2 = (const float*)d_in[10];
    float* y = (float*)d_out;

    se_reduce<<<NPLANE, 256>>>(x);
    se_excite<<<BB, 256>>>(w1, g1, b1, m1, v1, w2, g2, b2, m2, v2);
    se_scale<<<NPLANE / 4, 256>>>(x, y);
}